// round 1
// baseline (speedup 1.0000x reference)
#include <cuda_runtime.h>
#include <cuda_bf16.h>

// Problem constants (fixed shapes from reference)
#define BB    16
#define TT    8
#define CIN   64
#define COUT  64
#define HH    56
#define WW    56
#define KDIM  576        // CIN * 3 * 3
#define NPIX  3136       // 56*56
#define CHW   25088      // TT * NPIX (stride between consecutive ci planes at fixed b,t)

// Transposed weights: wT[k][m], k = ci*9 + kh*3 + kw, m = c_out.
// __device__ global scratch (no cudaMalloc allowed).
__device__ float g_wT[KDIM * COUT];

__global__ void transpose_w_kernel(const float* __restrict__ w) {
    int idx = blockIdx.x * blockDim.x + threadIdx.x;
    if (idx < KDIM * COUT) {
        int k = idx / COUT;
        int m = idx - k * COUT;
        g_wT[idx] = w[m * KDIM + k];
    }
}

// Implicit-GEMM fp32 conv.
// Grid: (49 pixel-tiles, 128 images). Block: 256 threads.
// Block computes C[64 x 64]: all c_out for 64 consecutive pixels of one image.
__global__ __launch_bounds__(256) void tada_conv_kernel(
    const float* __restrict__ x,     // [B, CIN, T, H, W]
    const float* __restrict__ rw,    // [B, CIN, T, 1, 1]
    float* __restrict__ out)         // [B, COUT, T, H, W]
{
    __shared__ float As[32][64];     // [kk][m]
    __shared__ float Bs[32][64];     // [kk][n]
    __shared__ float sscale[CIN];

    const int tile = blockIdx.x;     // 0..48
    const int img  = blockIdx.y;     // 0..127  (img = b*T + t)
    const int b    = img >> 3;
    const int t    = img & 7;
    const int tid  = threadIdx.x;

    // Per-(image, ci) routing scale -> smem
    if (tid < CIN) {
        sscale[tid] = rw[(b * CIN + tid) * TT + t];
    }

    const int p0 = tile * 64;                 // first pixel of this tile
    const int m0 = (tid >> 4) * 4;            // c_out sub-tile
    const int n0 = (tid & 15) * 4;            // pixel sub-tile

    // Base of x for (b, ci=0, t): plane for ci is xbase + ci*CHW
    const float* xbase = x + ((long)b * CIN * TT + t) * NPIX;

    float acc[4][4] = {};

    __syncthreads();  // sscale visible before first B-load

    for (int k0 = 0; k0 < KDIM; k0 += 32) {
        // ---- Load A chunk: wT[k0+kk][m] -> As[kk][m] (coalesced, conflict-free)
        #pragma unroll
        for (int q = 0; q < 8; q++) {
            int idx = q * 256 + tid;          // 0..2047
            int kk  = idx >> 6;
            int m   = idx & 63;
            As[kk][m] = g_wT[(k0 + kk) * COUT + m];
        }
        // ---- Load B chunk: on-the-fly scaled im2col -> Bs[kk][n]
        #pragma unroll
        for (int q = 0; q < 8; q++) {
            int idx = q * 256 + tid;
            int kk  = idx >> 6;
            int n   = idx & 63;
            int k   = k0 + kk;
            int ci  = k / 9;
            int r   = k - ci * 9;
            int kh  = r / 3;
            int kw  = r - kh * 3;
            int p   = p0 + n;
            int y   = p / WW;
            int xx  = p - y * WW;
            int iy  = y + kh - 1;
            int ix  = xx + kw - 1;
            float v = 0.0f;
            if ((unsigned)iy < (unsigned)HH && (unsigned)ix < (unsigned)WW) {
                v = xbase[ci * CHW + iy * WW + ix] * sscale[ci];
            }
            Bs[kk][n] = v;
        }
        __syncthreads();

        // ---- FFMA mainloop: 32 kk x (4x4) per thread
        #pragma unroll
        for (int kk = 0; kk < 32; kk++) {
            float4 av = *(const float4*)&As[kk][m0];
            float4 bv = *(const float4*)&Bs[kk][n0];
            float af[4] = {av.x, av.y, av.z, av.w};
            float bf[4] = {bv.x, bv.y, bv.z, bv.w};
            #pragma unroll
            for (int i = 0; i < 4; i++)
                #pragma unroll
                for (int j = 0; j < 4; j++)
                    acc[i][j] += af[i] * bf[j];
        }
        __syncthreads();
    }

    // ---- Epilogue: out[b][m][t][p]  (float4 stores, p0+n0 is 4-aligned)
    #pragma unroll
    for (int i = 0; i < 4; i++) {
        int m = m0 + i;
        float4 v = make_float4(acc[i][0], acc[i][1], acc[i][2], acc[i][3]);
        *(float4*)&out[((long)(b * COUT + m) * TT + t) * NPIX + p0 + n0] = v;
    }
}

extern "C" void kernel_launch(void* const* d_in, const int* in_sizes, int n_in,
                              void* d_out, int out_size) {
    const float* x  = (const float*)d_in[0];   // [16,64,8,56,56]
    const float* rw = (const float*)d_in[1];   // [16,64,8,1,1]
    const float* w  = (const float*)d_in[2];   // [64,64,3,3]
    float* out = (float*)d_out;                // [16,64,8,56,56]

    transpose_w_kernel<<<(KDIM * COUT + 255) / 256, 256>>>(w);

    dim3 grid(NPIX / 64, BB * TT);             // (49, 128)
    tada_conv_kernel<<<grid, 256>>>(x, rw, out);
}

// round 5
// speedup vs baseline: 4.2796x; 4.2796x over previous
#include <cuda_runtime.h>
#include <cstdint>

// ---------------- problem constants ----------------
#define NIMG   128          // b*t
#define PADW   58           // padded row width
#define PROWS  60           // padded rows per image
#define PPLANE (PROWS*PADW) // 3480
#define QVALID 3248         // 56*58
#define TPI    26           // 128-position tiles per image
#define NTILES (NIMG*TPI)   // 3328
#define GRIDX  148

// smem float-index layout
#define F_WIN   256                 // byte 1024; window 256 rows x pitch 68 floats
#define WPITCH  68
#define F_WS    (256 + 256*68)      // 17664; weights 64 rows x pitch 580 floats
#define WSPITCH 580
#define SMEM_TOTAL ((F_WS + 64*WSPITCH) * 4)   // 219136 bytes
#define WIN_BYTES  65536            // 256 rows x 256B payload
#define WS_BYTES   (64*WSPITCH*4)   // 148480

// ---------------- device scratch ----------------
__device__ __align__(256) float g_xp[(size_t)NIMG * PPLANE * 64];  // NHWC padded, scaled, tf32-rounded
__device__ __align__(256) float g_ws[64 * WSPITCH];                // weight image [co][s*64+ci], tf32

// ---------------- PTX helpers ----------------
__device__ __forceinline__ uint32_t smem_u32(const void* p) {
    uint32_t a;
    asm("{ .reg .u64 t; cvta.to.shared.u64 t, %1; cvt.u32.u64 %0, t; }" : "=r"(a) : "l"(p));
    return a;
}
#define MBAR_INIT(a, c) asm volatile("mbarrier.init.shared.b64 [%0], %1;" :: "r"(a), "r"(c) : "memory")
#define MBAR_EXPECT_TX(a, n) asm volatile("mbarrier.arrive.expect_tx.shared.b64 _, [%0], %1;" :: "r"(a), "r"(n) : "memory")
#define MBAR_WAIT(a, ph) do { \
    uint32_t _m = (a); uint32_t _p = (ph); uint32_t _d; \
    asm volatile("{\n\t.reg .pred p;\n\tmbarrier.try_wait.parity.shared.b64 p, [%1], %2;\n\tselp.b32 %0,1,0,p;\n\t}" \
        : "=r"(_d) : "r"(_m), "r"(_p) : "memory"); \
    if (!_d) { asm volatile("{\n\t.reg .pred P1;\n\tWL%=:\n\tmbarrier.try_wait.parity.shared.b64 P1, [%0], %1;\n\t@P1 bra.uni WD%=;\n\tbra.uni WL%=;\n\tWD%=:\n\t}" \
        :: "r"(_m), "r"(_p) : "memory"); } \
} while (0)

__device__ __forceinline__ void bulkcp(uint32_t dst, const void* src, uint32_t bytes, uint32_t mbar) {
    asm volatile("cp.async.bulk.shared::cta.global.mbarrier::complete_tx::bytes [%0], [%1], %2, [%3];"
        :: "r"(dst), "l"(src), "r"(bytes), "r"(mbar) : "memory");
}

__device__ __forceinline__ void mma8(float* d, const uint32_t* a, uint32_t b0, uint32_t b1) {
    asm volatile("mma.sync.aligned.m16n8k8.row.col.f32.tf32.tf32.f32 "
        "{%0,%1,%2,%3}, {%4,%5,%6,%7}, {%8,%9}, {%0,%1,%2,%3};"
        : "+f"(d[0]), "+f"(d[1]), "+f"(d[2]), "+f"(d[3])
        : "r"(a[0]), "r"(a[1]), "r"(a[2]), "r"(a[3]), "r"(b0), "r"(b1));
}

// ---------------- pre-kernel: x -> scaled, padded, NHWC, tf32-rounded ----------------
__global__ __launch_bounds__(256) void xprep_kernel(const float* __restrict__ x,
                                                    const float* __restrict__ rw) {
    __shared__ float s[64][33];
    const int img = blockIdx.x;          // 0..127
    const int iy  = blockIdx.y;          // 0..59
    const int ix0 = blockIdx.z * 32;     // 0 or 32
    const int b = img >> 3, t = img & 7;
    const int tid = threadIdx.x;
    const int xin_y = iy - 1;

    #pragma unroll
    for (int r = 0; r < 8; r++) {
        int idx = tid + r * 256;         // 2048 = 64ci x 32ix
        int ci = idx >> 5, ixo = idx & 31;
        int xin_x = ix0 + ixo - 1;
        float v = 0.0f;
        if ((unsigned)xin_y < 56u && (unsigned)xin_x < 56u)
            v = x[((b * 64 + ci) * 8 + t) * 3136 + xin_y * 56 + xin_x] *
                rw[(b * 64 + ci) * 8 + t];
        uint32_t u;
        asm("cvt.rna.tf32.f32 %0, %1;" : "=r"(u) : "f"(v));
        s[ci][ixo] = __uint_as_float(u);
    }
    __syncthreads();
    #pragma unroll
    for (int r = 0; r < 8; r++) {
        int idx = tid + r * 256;
        int c = idx & 63, ixo = idx >> 6;
        int ix = ix0 + ixo;
        if (ix < PADW)
            g_xp[((size_t)img * PPLANE + iy * PADW + ix) * 64 + c] = s[c][ixo];
    }
}

// ---------------- pre-kernel: weights -> [co][s*64+ci] tf32 image ----------------
__global__ void wprep_kernel(const float* __restrict__ w) {
    int idx = blockIdx.x * blockDim.x + threadIdx.x;   // 64*576
    if (idx >= 64 * 576) return;
    int co = idx / 576;
    int k  = idx - co * 576;
    int s  = k >> 6, ci = k & 63;
    int dh = s / 3, dw = s - dh * 3;
    float v = w[co * 576 + ci * 9 + dh * 3 + dw];
    uint32_t u;
    asm("cvt.rna.tf32.f32 %0, %1;" : "=r"(u) : "f"(v));
    g_ws[co * WSPITCH + k] = __uint_as_float(u);
}

// ---------------- main persistent mma.sync kernel ----------------
__global__ __launch_bounds__(256, 1) void conv_main_kernel(float* __restrict__ out) {
    extern __shared__ float sm[];
    const uint32_t sbase = smem_u32(sm);
    const uint32_t wmbar = sbase + 16;
    const int tid  = threadIdx.x;
    const int wid  = tid >> 5;
    const int lane = tid & 31;
    const int g  = lane >> 2;      // 0..7
    const int tl = lane & 3;       // 0..3
    const int wco = (wid & 1) * 32;        // c_out offset (2 warps)
    const int wpx = (wid >> 1) * 32;       // pixel offset (4 warps)

    if (tid == 0) MBAR_INIT(wmbar, 1);
    __syncthreads();
    // prologue phase 0: weights image + first window
    if (tid == 0) MBAR_EXPECT_TX(wmbar, (uint32_t)(WS_BYTES + WIN_BYTES));
    __syncthreads();
    if (tid < 64)
        bulkcp(sbase + F_WS * 4 + tid * (WSPITCH * 4),
               g_ws + tid * WSPITCH, WSPITCH * 4, wmbar);
    {
        const int tile0 = blockIdx.x;
        const int img = tile0 / TPI;
        const int q0  = (tile0 - img * TPI) * 128;
        bulkcp(sbase + F_WIN * 4 + tid * (WPITCH * 4),
               g_xp + ((size_t)img * PPLANE + q0 + tid) * 64, 256, wmbar);
    }

    const float* WIN = sm + F_WIN;
    const float* WS  = sm + F_WS;

    int i = 0;
    for (int tile = blockIdx.x; tile < NTILES; tile += GRIDX, i++) {
        MBAR_WAIT(wmbar, (uint32_t)(i & 1));

        float acc[2][4][4] = {};
        const float* arow0 = WS + (wco + g) * WSPITCH;        // mf0 rows g, g+8
        const float* arow1 = arow0 + 8 * WSPITCH;
        const float* arow2 = arow0 + 16 * WSPITCH;            // mf1 rows g+16, g+24
        const float* arow3 = arow0 + 24 * WSPITCH;

        #pragma unroll 1
        for (int s = 0; s < 9; s++) {
            const int dh = s / 3, dw = s - dh * 3;
            const float* brow = WIN + (dh * PADW + dw + wpx + g) * WPITCH;
            const int kb = s * 64;
            #pragma unroll
            for (int kc = 0; kc < 8; kc++) {
                const int k0 = kb + kc * 8 + tl;
                uint32_t a0[4], a1[4];
                a0[0] = __float_as_uint(arow0[k0]);
                a0[1] = __float_as_uint(arow1[k0]);
                a0[2] = __float_as_uint(arow0[k0 + 4]);
                a0[3] = __float_as_uint(arow1[k0 + 4]);
                a1[0] = __float_as_uint(arow2[k0]);
                a1[1] = __float_as_uint(arow3[k0]);
                a1[2] = __float_as_uint(arow2[k0 + 4]);
                a1[3] = __float_as_uint(arow3[k0 + 4]);
                const int c0 = kc * 8 + tl;
                #pragma unroll
                for (int j = 0; j < 4; j++) {
                    uint32_t b0 = __float_as_uint(brow[j * (8 * WPITCH) + c0]);
                    uint32_t b1 = __float_as_uint(brow[j * (8 * WPITCH) + c0 + 4]);
                    mma8(acc[0][j], a0, b0, b1);
                    mma8(acc[1][j], a1, b0, b1);
                }
            }
        }

        __syncthreads();                       // all warps done reading window
        const int ntile = tile + GRIDX;
        if (ntile < NTILES && tid == 0) MBAR_EXPECT_TX(wmbar, WIN_BYTES);
        __syncthreads();                       // expect_tx before any complete_tx
        if (ntile < NTILES) {
            const int nimg = ntile / TPI;
            const int nq0  = (ntile - nimg * TPI) * 128;
            bulkcp(sbase + F_WIN * 4 + tid * (WPITCH * 4),
                   g_xp + ((size_t)nimg * PPLANE + nq0 + tid) * 64, 256, wmbar);
        }

        // epilogue (overlaps staging): C rows=c_out, cols=pixels -> STG.64 pairs
        {
            const int img = tile / TPI;
            const int q0  = (tile - img * TPI) * 128;
            const int bb = img >> 3, tt = img & 7;
            #pragma unroll
            for (int mf = 0; mf < 2; mf++) {
                #pragma unroll
                for (int j = 0; j < 4; j++) {
                    const int n = wpx + j * 8 + tl * 2;
                    const int q = q0 + n;
                    const int y = q / PADW;
                    const int x = q - y * PADW;
                    if (x < 56 && q < QVALID) {
                        const int co = wco + mf * 16 + g;
                        const long base = ((long)(bb * 64 + co) * 8 + tt) * 3136 + y * 56 + x;
                        *(float2*)&out[base] = make_float2(acc[mf][j][0], acc[mf][j][1]);
                        *(float2*)&out[base + 8L * 8 * 3136] = make_float2(acc[mf][j][2], acc[mf][j][3]);
                    }
                }
            }
        }
    }
}

// ---------------- launch ----------------
extern "C" void kernel_launch(void* const* d_in, const int* in_sizes, int n_in,
                              void* d_out, int out_size) {
    const float* x  = (const float*)d_in[0];   // [16,64,8,56,56]
    const float* rw = (const float*)d_in[1];   // [16,64,8,1,1]
    const float* w  = (const float*)d_in[2];   // [64,64,3,3]
    float* out = (float*)d_out;                // [16,64,8,56,56]

    cudaFuncSetAttribute(conv_main_kernel, cudaFuncAttributeMaxDynamicSharedMemorySize, SMEM_TOTAL);

    dim3 xg(NIMG, PROWS, 2);
    xprep_kernel<<<xg, 256>>>(x, rw);
    wprep_kernel<<<(64 * 576 + 255) / 256, 256>>>(w);
    conv_main_kernel<<<GRIDX, 256, SMEM_TOTAL>>>(out);
}